// round 1
// baseline (speedup 1.0000x reference)
#include <cuda_runtime.h>
#include <math.h>

#define BATCH 16
#define CDIM  128
#define NHEADS 4
#define HDIM  32
#define NPIX  4096
#define OQKV  384

// ---- scratch (device globals: allocation-free) ----
__device__ float g_q[BATCH * CDIM * NPIX];      // 33.5 MB  q (raw then softmaxed, in-place)
__device__ float g_k[BATCH * CDIM * NPIX];      // 33.5 MB  exp(k)
__device__ float g_v[BATCH * CDIM * NPIX];      // 33.5 MB  v
__device__ float g_ctx[BATCH * NHEADS * HDIM * HDIM]; // unnormalized context
__device__ float g_z[BATCH * NHEADS * HDIM];          // softmax denominators for k
__device__ float g_M[BATCH * CDIM * CDIM];            // folded w_out @ ctx
__device__ float g_stats[BATCH * 2];                  // per-batch sum, sumsq

// ---------------------------------------------------------------------------
__global__ __launch_bounds__(256) void zero_scratch() {
    int i = blockIdx.x * 256 + threadIdx.x;
    if (i < BATCH * NHEADS * HDIM * HDIM) g_ctx[i] = 0.f;
    if (i < BATCH * NHEADS * HDIM) g_z[i] = 0.f;
    if (i < BATCH * 2) g_stats[i] = 0.f;
}

// ---------------------------------------------------------------------------
// QKV GEMM: qkv[b,o,n] = sum_c w[o,c] * x[b,c,n];  o in [0,384)
// 64x64 block tile, 4x4 per thread, BK=16. Epilogue routes to q/k/v, exp() on k.
__global__ __launch_bounds__(256) void qkv_gemm(const float* __restrict__ x,
                                                const float* __restrict__ w) {
    __shared__ float As[16][68];   // [k][o], padded (16B-aligned rows)
    __shared__ float Bs[16][64];   // [k][n]
    int b  = blockIdx.z;
    int o0 = blockIdx.y * 64;
    int n0 = blockIdx.x * 64;
    int tid = threadIdx.x;
    int ty = tid >> 4, tx = tid & 15;
    int arow = tid >> 2, acol = (tid & 3) << 2;   // A: 64 rows x 16 cols
    int brow = tid >> 4, bcol = (tid & 15) << 2;  // B: 16 rows x 64 cols
    const float* xb = x + (size_t)b * CDIM * NPIX;

    float acc[4][4];
#pragma unroll
    for (int i = 0; i < 4; i++)
#pragma unroll
        for (int j = 0; j < 4; j++) acc[i][j] = 0.f;

    for (int k0 = 0; k0 < CDIM; k0 += 16) {
        float4 a4 = *(const float4*)(w + (size_t)(o0 + arow) * CDIM + k0 + acol);
        float4 b4 = *(const float4*)(xb + (size_t)(k0 + brow) * NPIX + n0 + bcol);
        __syncthreads();
        As[acol + 0][arow] = a4.x;
        As[acol + 1][arow] = a4.y;
        As[acol + 2][arow] = a4.z;
        As[acol + 3][arow] = a4.w;
        *(float4*)&Bs[brow][bcol] = b4;
        __syncthreads();
#pragma unroll
        for (int kk = 0; kk < 16; kk++) {
            float4 av = *(const float4*)&As[kk][ty << 2];
            float4 bv = *(const float4*)&Bs[kk][tx << 2];
            float a[4] = {av.x, av.y, av.z, av.w};
            float bb[4] = {bv.x, bv.y, bv.z, bv.w};
#pragma unroll
            for (int i = 0; i < 4; i++)
#pragma unroll
                for (int j = 0; j < 4; j++) acc[i][j] += a[i] * bb[j];
        }
    }

    // whole block is inside one 128-row section (o0 multiple of 64)
    int sec = o0 >> 7;
    float* dst = (sec == 0) ? g_q : (sec == 1) ? g_k : g_v;
    int obase = (o0 & 127) + (ty << 2);
    size_t nidx = (size_t)n0 + (tx << 2);
#pragma unroll
    for (int i = 0; i < 4; i++) {
        float4 v4 = {acc[i][0], acc[i][1], acc[i][2], acc[i][3]};
        if (sec == 1) {
            v4.x = expf(v4.x); v4.y = expf(v4.y);
            v4.z = expf(v4.z); v4.w = expf(v4.w);
        }
        *(float4*)&dst[((size_t)b * CDIM + obase + i) * NPIX + nidx] = v4;
    }
}

// ---------------------------------------------------------------------------
// Softmax of q over d (32 values, stride NPIX), times scale. In-place.
// One thread per (b,h,n); coalesced across n.
__global__ __launch_bounds__(256) void q_softmax() {
    int bh = blockIdx.x >> 4;                  // 0..63 = b*4+h
    int n = ((blockIdx.x & 15) << 8) + threadIdx.x;
    float* base = g_q + (size_t)bh * HDIM * NPIX + n;
    float vals[HDIM];
    float m = -1e30f;
#pragma unroll
    for (int d = 0; d < HDIM; d++) {
        vals[d] = base[(size_t)d * NPIX];
        m = fmaxf(m, vals[d]);
    }
    float s = 0.f;
#pragma unroll
    for (int d = 0; d < HDIM; d++) {
        vals[d] = expf(vals[d] - m);
        s += vals[d];
    }
    float inv = 0.17677669529663687f / s;      // 32^-0.5 / sum
#pragma unroll
    for (int d = 0; d < HDIM; d++) base[(size_t)d * NPIX] = vals[d] * inv;
}

// ---------------------------------------------------------------------------
// ctx[bh,d,e] += sum_n ek[d,n]*v[e,n];  z[bh,d] += sum_n ek[d,n]
// grid (64 bh, 8 n-chunks of 512). Atomic accumulation into zeroed scratch.
__global__ __launch_bounds__(256) void kv_context() {
    __shared__ float ekS[HDIM][65];
    __shared__ float vT[64][36];               // transposed [n][e], padded
    int bh = blockIdx.x;
    int nc = blockIdx.y;
    const float* kb = g_k + (size_t)bh * HDIM * NPIX + nc * 512;
    const float* vb = g_v + (size_t)bh * HDIM * NPIX + nc * 512;
    int tid = threadIdx.x;
    int d = tid >> 3, e0 = (tid & 7) << 2;
    float a0 = 0, a1 = 0, a2 = 0, a3 = 0, zacc = 0;
    for (int s = 0; s < 8; s++) {
        __syncthreads();
        for (int i = tid; i < 2048; i += 256) {
            int r = i >> 6, cc = i & 63;
            ekS[r][cc] = kb[(size_t)r * NPIX + s * 64 + cc];
            vT[cc][r]  = vb[(size_t)r * NPIX + s * 64 + cc];
        }
        __syncthreads();
#pragma unroll 8
        for (int n = 0; n < 64; n++) {
            float kv = ekS[d][n];
            zacc += kv;
            float4 vv = *(const float4*)&vT[n][e0];
            a0 += kv * vv.x; a1 += kv * vv.y;
            a2 += kv * vv.z; a3 += kv * vv.w;
        }
    }
    float* cp = g_ctx + (size_t)bh * 1024 + d * 32 + e0;
    atomicAdd(cp + 0, a0); atomicAdd(cp + 1, a1);
    atomicAdd(cp + 2, a2); atomicAdd(cp + 3, a3);
    if ((tid & 7) == 0) atomicAdd(&g_z[bh * 32 + d], zacc);  // each d counted once per block
}

// ---------------------------------------------------------------------------
// M[b][c, h*32+d] = sum_e w_out[c, h*32+e] * ctx[b,h,d,e] / z[b,h,d]
__global__ __launch_bounds__(128) void fold(const float* __restrict__ w_out) {
    __shared__ float ctxS[NHEADS][HDIM][HDIM];
    __shared__ float zS[CDIM];
    int b = blockIdx.x, tid = threadIdx.x;
    zS[tid] = g_z[b * CDIM + tid];
    __syncthreads();
    for (int i = tid; i < NHEADS * HDIM * HDIM; i += 128) {
        int h = i >> 10, dd = (i >> 5) & 31, e = i & 31;
        ctxS[h][dd][e] = g_ctx[(size_t)b * 4096 + i] / zS[(h << 5) + dd];
    }
    __syncthreads();
    int c = tid;
    const float* wrow = w_out + (size_t)c * CDIM;
    for (int h = 0; h < NHEADS; h++) {
        float acc[HDIM];
#pragma unroll
        for (int dd = 0; dd < HDIM; dd++) acc[dd] = 0.f;
        for (int e = 0; e < HDIM; e++) {
            float wv = wrow[(h << 5) + e];
#pragma unroll
            for (int dd = 0; dd < HDIM; dd++) acc[dd] += wv * ctxS[h][dd][e];
        }
#pragma unroll
        for (int dd = 0; dd < HDIM; dd++)
            g_M[(size_t)b * (CDIM * CDIM) + (size_t)c * CDIM + (h << 5) + dd] = acc[dd];
    }
}

// ---------------------------------------------------------------------------
// final[b,c,n] = sum_o M[b][c,o] * q[b,o,n] + b_out[c]; also per-batch sum/sumsq.
__global__ __launch_bounds__(256) void final_gemm(const float* __restrict__ b_out,
                                                  float* __restrict__ out) {
    __shared__ float As[16][68];
    __shared__ float Bs[16][64];
    __shared__ float red[2][8];
    int b  = blockIdx.z;
    int c0 = blockIdx.y * 64;
    int n0 = blockIdx.x * 64;
    int tid = threadIdx.x;
    int ty = tid >> 4, tx = tid & 15;
    int arow = tid >> 2, acol = (tid & 3) << 2;
    int brow = tid >> 4, bcol = (tid & 15) << 2;
    const float* Ab = g_M + (size_t)b * (CDIM * CDIM);
    const float* Bb = g_q + (size_t)b * CDIM * NPIX;

    float acc[4][4];
#pragma unroll
    for (int i = 0; i < 4; i++)
#pragma unroll
        for (int j = 0; j < 4; j++) acc[i][j] = 0.f;

    for (int k0 = 0; k0 < CDIM; k0 += 16) {
        float4 a4 = *(const float4*)(Ab + (size_t)(c0 + arow) * CDIM + k0 + acol);
        float4 b4 = *(const float4*)(Bb + (size_t)(k0 + brow) * NPIX + n0 + bcol);
        __syncthreads();
        As[acol + 0][arow] = a4.x;
        As[acol + 1][arow] = a4.y;
        As[acol + 2][arow] = a4.z;
        As[acol + 3][arow] = a4.w;
        *(float4*)&Bs[brow][bcol] = b4;
        __syncthreads();
#pragma unroll
        for (int kk = 0; kk < 16; kk++) {
            float4 av = *(const float4*)&As[kk][ty << 2];
            float4 bv = *(const float4*)&Bs[kk][tx << 2];
            float a[4] = {av.x, av.y, av.z, av.w};
            float bb[4] = {bv.x, bv.y, bv.z, bv.w};
#pragma unroll
            for (int i = 0; i < 4; i++)
#pragma unroll
                for (int j = 0; j < 4; j++) acc[i][j] += a[i] * bb[j];
        }
    }

    float s1 = 0.f, s2 = 0.f;
    size_t nidx = (size_t)n0 + (tx << 2);
#pragma unroll
    for (int i = 0; i < 4; i++) {
        int c = c0 + (ty << 2) + i;
        float bias = b_out[c];
        float4 v4 = {acc[i][0] + bias, acc[i][1] + bias,
                     acc[i][2] + bias, acc[i][3] + bias};
        s1 += v4.x + v4.y + v4.z + v4.w;
        s2 += v4.x * v4.x + v4.y * v4.y + v4.z * v4.z + v4.w * v4.w;
        *(float4*)&out[((size_t)b * CDIM + c) * NPIX + nidx] = v4;
    }
#pragma unroll
    for (int off = 16; off; off >>= 1) {
        s1 += __shfl_down_sync(0xffffffffu, s1, off);
        s2 += __shfl_down_sync(0xffffffffu, s2, off);
    }
    if ((tid & 31) == 0) { red[0][tid >> 5] = s1; red[1][tid >> 5] = s2; }
    __syncthreads();
    if (tid == 0) {
        float t1 = 0.f, t2 = 0.f;
#pragma unroll
        for (int wi = 0; wi < 8; wi++) { t1 += red[0][wi]; t2 += red[1][wi]; }
        atomicAdd(&g_stats[2 * b], t1);
        atomicAdd(&g_stats[2 * b + 1], t2);
    }
}

// ---------------------------------------------------------------------------
// GroupNorm (1 group over C*N per batch), in-place on out.
__global__ __launch_bounds__(256) void gn_apply(const float* __restrict__ gnw,
                                                const float* __restrict__ gnb,
                                                float* __restrict__ out) {
    size_t idx = ((size_t)blockIdx.x * 256 + threadIdx.x) << 2;
    int b = (int)(idx >> 19);        // C*N = 2^19
    int c = (int)((idx >> 12) & 127);
    const float inv_cnt = 1.f / (float)(CDIM * NPIX);
    float mean = g_stats[2 * b] * inv_cnt;
    float var  = g_stats[2 * b + 1] * inv_cnt - mean * mean;
    float rstd = rsqrtf(var + 1e-5f);
    float scale = rstd * gnw[c];
    float shift = gnb[c] - mean * scale;
    float4 v = *(const float4*)&out[idx];
    v.x = v.x * scale + shift;
    v.y = v.y * scale + shift;
    v.z = v.z * scale + shift;
    v.w = v.w * scale + shift;
    *(float4*)&out[idx] = v;
}

// ---------------------------------------------------------------------------
extern "C" void kernel_launch(void* const* d_in, const int* in_sizes, int n_in,
                              void* d_out, int out_size) {
    (void)in_sizes; (void)n_in; (void)out_size;
    const float* x     = (const float*)d_in[0];
    const float* w_qkv = (const float*)d_in[1];
    const float* w_out = (const float*)d_in[2];
    const float* b_out = (const float*)d_in[3];
    const float* gnw   = (const float*)d_in[4];
    const float* gnb   = (const float*)d_in[5];
    float* out = (float*)d_out;

    zero_scratch<<<256, 256>>>();
    qkv_gemm<<<dim3(NPIX / 64, OQKV / 64, BATCH), 256>>>(x, w_qkv);
    q_softmax<<<BATCH * NHEADS * (NPIX / 256), 256>>>();
    kv_context<<<dim3(BATCH * NHEADS, 8), 256>>>();
    fold<<<BATCH, 128>>>(w_out);
    final_gemm<<<dim3(NPIX / 64, CDIM / 64, BATCH), 256>>>(b_out, out);
    gn_apply<<<(BATCH * CDIM * NPIX) / (256 * 4), 256>>>(gnw, gnb, out);
}

// round 3
// speedup vs baseline: 1.4861x; 1.4861x over previous
#include <cuda_runtime.h>
#include <cuda_bf16.h>
#include <math.h>
#include <stdint.h>

#define BATCH 16
#define CDIM  128
#define NHEADS 4
#define HDIM  32
#define NPIX  4096
#define OQKV  384

// ---- scratch (device globals: allocation-free) ----
__device__ float g_q[BATCH * CDIM * NPIX];            // raw q from qkv
__device__ float g_k[BATCH * CDIM * NPIX];            // exp(k)
__device__ float g_v[BATCH * CDIM * NPIX];            // v
__device__ float g_ctx[BATCH * NHEADS * HDIM * HDIM];
__device__ float g_z[BATCH * NHEADS * HDIM];
__device__ float g_M[BATCH * CDIM * CDIM];
__device__ float g_stats[BATCH * 2];

// bf16 split operands
__device__ __nv_bfloat16 g_wh[OQKV * CDIM];
__device__ __nv_bfloat16 g_wl[OQKV * CDIM];
__device__ __nv_bfloat16 g_xh[BATCH * NPIX * CDIM];   // [b][n][c]
__device__ __nv_bfloat16 g_xl[BATCH * NPIX * CDIM];
__device__ __nv_bfloat16 g_qh[BATCH * NPIX * CDIM];   // [b][n][o] softmaxed q
__device__ __nv_bfloat16 g_ql[BATCH * NPIX * CDIM];
__device__ __nv_bfloat16 g_mh[BATCH * CDIM * CDIM];
__device__ __nv_bfloat16 g_ml[BATCH * CDIM * CDIM];

__device__ __forceinline__ uint32_t smem_u32(const void* p) {
    uint32_t a;
    asm("{ .reg .u64 t; cvta.to.shared.u64 t, %1; cvt.u32.u64 %0, t; }"
        : "=r"(a) : "l"(p));
    return a;
}

__device__ __forceinline__ void ldm_x4(uint32_t* r, uint32_t addr) {
    asm volatile("ldmatrix.sync.aligned.m8n8.x4.shared.b16 {%0,%1,%2,%3}, [%4];"
                 : "=r"(r[0]), "=r"(r[1]), "=r"(r[2]), "=r"(r[3]) : "r"(addr));
}
__device__ __forceinline__ void mma16816(float* c, const uint32_t* a,
                                         uint32_t b0, uint32_t b1) {
    asm volatile(
        "mma.sync.aligned.m16n8k16.row.col.f32.bf16.bf16.f32 "
        "{%0,%1,%2,%3}, {%4,%5,%6,%7}, {%8,%9}, {%0,%1,%2,%3};"
        : "+f"(c[0]), "+f"(c[1]), "+f"(c[2]), "+f"(c[3])
        : "r"(a[0]), "r"(a[1]), "r"(a[2]), "r"(a[3]), "r"(b0), "r"(b1));
}

// smem tile: 128 rows x 64 bf16, row stride 9 x 16B = 144B
#define SROW 9
#define TILE_BYTES (128 * SROW * 16)

// 3-term split mainloop: C(128x128) += [Ah,Ah,Al](128x128) @ [Bh,Bl,Bh]^T(128x128)
// A row-major [row][k], B row-major [n][k] (= col-major kxn). acc[2][8][4].
__device__ __forceinline__ void gemm_mainloop(
    const __nv_bfloat16* __restrict__ Ah, const __nv_bfloat16* __restrict__ Al,
    const __nv_bfloat16* __restrict__ Bh, const __nv_bfloat16* __restrict__ Bl,
    float acc[2][8][4], char* sA, char* sB) {
    int tid = threadIdx.x;
    int lane = tid & 31, wid = tid >> 5;
    int warp_m = (wid & 3) * 32, warp_n = (wid >> 2) * 64;
    uint32_t sA32 = smem_u32(sA), sB32 = smem_u32(sB);

    const __nv_bfloat16* Asrc[6] = {Ah, Ah + 64, Ah, Ah + 64, Al, Al + 64};
    const __nv_bfloat16* Bsrc[6] = {Bh, Bh + 64, Bl, Bl + 64, Bh, Bh + 64};

    int row4[4], u4[4], soff4[4];
#pragma unroll
    for (int i = 0; i < 4; i++) {
        int lin = tid + (i << 8);
        row4[i] = lin >> 3;
        u4[i] = lin & 7;
        soff4[i] = (row4[i] * SROW + u4[i]) * 16;
    }

    uint4 pa[4], pb[4];
#pragma unroll
    for (int i = 0; i < 4; i++) {
        pa[i] = ((const uint4*)Asrc[0])[row4[i] * 16 + u4[i]];
        pb[i] = ((const uint4*)Bsrc[0])[row4[i] * 16 + u4[i]];
    }

    // ldmatrix lane address components
    int a_row = lane & 15, a_hi = lane >> 4;                 // A: row, k-unit add
    int b_n = (lane & 7) + ((lane >> 4) << 3);               // B: n
    int b_ku = (lane >> 3) & 1;

    for (int c = 0; c < 6; c++) {
        __syncthreads();
#pragma unroll
        for (int i = 0; i < 4; i++) {
            *(uint4*)(sA + soff4[i]) = pa[i];
            *(uint4*)(sB + soff4[i]) = pb[i];
        }
        __syncthreads();
        if (c < 5) {
#pragma unroll
            for (int i = 0; i < 4; i++) {
                pa[i] = ((const uint4*)Asrc[c + 1])[row4[i] * 16 + u4[i]];
                pb[i] = ((const uint4*)Bsrc[c + 1])[row4[i] * 16 + u4[i]];
            }
        }
#pragma unroll
        for (int kk = 0; kk < 4; kk++) {
            uint32_t af[2][4];
#pragma unroll
            for (int mi = 0; mi < 2; mi++) {
                uint32_t addr = sA32 +
                    ((warp_m + mi * 16 + a_row) * SROW + kk * 2 + a_hi) * 16;
                ldm_x4(af[mi], addr);
            }
            uint32_t bf[8][2];
#pragma unroll
            for (int nj = 0; nj < 4; nj++) {
                uint32_t r[4];
                uint32_t addr = sB32 +
                    ((warp_n + nj * 16 + b_n) * SROW + kk * 2 + b_ku) * 16;
                ldm_x4(r, addr);
                bf[nj * 2 + 0][0] = r[0]; bf[nj * 2 + 0][1] = r[1];
                bf[nj * 2 + 1][0] = r[2]; bf[nj * 2 + 1][1] = r[3];
            }
#pragma unroll
            for (int mi = 0; mi < 2; mi++)
#pragma unroll
                for (int ni = 0; ni < 8; ni++)
                    mma16816(acc[mi][ni], af[mi], bf[ni][0], bf[ni][1]);
        }
    }
}

// ===========================================================================
__global__ __launch_bounds__(256) void zero_scratch() {
    int i = blockIdx.x * 256 + threadIdx.x;
    if (i < BATCH * NHEADS * HDIM * HDIM) g_ctx[i] = 0.f;
    if (i < BATCH * NHEADS * HDIM) g_z[i] = 0.f;
    if (i < BATCH * 2) g_stats[i] = 0.f;
}

__global__ __launch_bounds__(256) void split_w(const float* __restrict__ w) {
    int i = blockIdx.x * 256 + threadIdx.x;
    float v = w[i];
    __nv_bfloat16 hi = __float2bfloat16(v);
    g_wh[i] = hi;
    g_wl[i] = __float2bfloat16(v - __bfloat162float(hi));
}

__global__ __launch_bounds__(256) void split_m_k() {
    int i = blockIdx.x * 256 + threadIdx.x;
    float v = g_M[i];
    __nv_bfloat16 hi = __float2bfloat16(v);
    g_mh[i] = hi;
    g_ml[i] = __float2bfloat16(v - __bfloat162float(hi));
}

// x [b][c][n] fp32 -> xh/xl [b][n][c] bf16 (transpose + split)
__global__ __launch_bounds__(256) void split_x(const float* __restrict__ x) {
    __shared__ float sm[32][33];
    int b = blockIdx.z, c0 = blockIdx.y * 32, n0 = blockIdx.x * 32;
    int tid = threadIdx.x;
    const float* xb = x + ((size_t)b * CDIM + c0) * NPIX + n0;
    int r = tid >> 5, col = tid & 31;
#pragma unroll
    for (int p = 0; p < 4; p++)
        sm[r + 8 * p][col] = xb[(size_t)(r + 8 * p) * NPIX + col];
    __syncthreads();
    int wid = tid >> 5, lane = tid & 31;
    for (int nl = wid; nl < 32; nl += 8) {
        float v = sm[lane][nl];
        __nv_bfloat16 hi = __float2bfloat16(v);
        __nv_bfloat16 lo = __float2bfloat16(v - __bfloat162float(hi));
        size_t o = ((size_t)b * NPIX + n0 + nl) * CDIM + c0 + lane;
        g_xh[o] = hi; g_xl[o] = lo;
    }
}

// ---------------------------------------------------------------------------
// QKV: C[b](384x4096) = W(384x128) @ X[b](128x4096). grid (32, 3, 16).
__global__ __launch_bounds__(256) void qkv_mma() {
    __shared__ char sA[TILE_BYTES];
    __shared__ char sB[TILE_BYTES];
    int n0 = blockIdx.x * 128, mt = blockIdx.y, b = blockIdx.z;
    float acc[2][8][4];
#pragma unroll
    for (int mi = 0; mi < 2; mi++)
#pragma unroll
        for (int ni = 0; ni < 8; ni++)
#pragma unroll
            for (int j = 0; j < 4; j++) acc[mi][ni][j] = 0.f;

    gemm_mainloop(g_wh + (size_t)mt * 128 * CDIM, g_wl + (size_t)mt * 128 * CDIM,
                  g_xh + ((size_t)b * NPIX + n0) * CDIM,
                  g_xl + ((size_t)b * NPIX + n0) * CDIM, acc, sA, sB);

    int tid = threadIdx.x, lane = tid & 31, wid = tid >> 5;
    int warp_m = (wid & 3) * 32, warp_n = (wid >> 2) * 64;
    int grp = lane >> 2, qid = lane & 3;
    float* dst = (mt == 0) ? g_q : (mt == 1) ? g_k : g_v;
    bool do_exp = (mt == 1);
#pragma unroll
    for (int mi = 0; mi < 2; mi++) {
        int r0 = warp_m + mi * 16 + grp;
#pragma unroll
        for (int ni = 0; ni < 8; ni++) {
            int col = n0 + warp_n + ni * 8 + 2 * qid;
            float2 v0 = {acc[mi][ni][0], acc[mi][ni][1]};
            float2 v1 = {acc[mi][ni][2], acc[mi][ni][3]};
            if (do_exp) {
                v0.x = expf(v0.x); v0.y = expf(v0.y);
                v1.x = expf(v1.x); v1.y = expf(v1.y);
            }
            *(float2*)&dst[((size_t)b * CDIM + r0) * NPIX + col] = v0;
            *(float2*)&dst[((size_t)b * CDIM + r0 + 8) * NPIX + col] = v1;
        }
    }
}

// ---------------------------------------------------------------------------
// softmax over d of raw q + scale, split+transpose to qh/ql [b][n][o]
__global__ __launch_bounds__(256) void softmax_split_q() {
    __shared__ float sm[256][33];
    int bh = blockIdx.x >> 4;
    int n0 = (blockIdx.x & 15) << 8;
    int tid = threadIdx.x;
    const float* base = g_q + (size_t)bh * HDIM * NPIX + n0 + tid;
    float vals[HDIM];
    float m = -1e30f;
#pragma unroll
    for (int d = 0; d < HDIM; d++) {
        vals[d] = base[(size_t)d * NPIX];
        m = fmaxf(m, vals[d]);
    }
    float s = 0.f;
#pragma unroll
    for (int d = 0; d < HDIM; d++) {
        vals[d] = expf(vals[d] - m);
        s += vals[d];
    }
    float inv = 0.17677669529663687f / s;   // 32^-0.5 / sum
#pragma unroll
    for (int d = 0; d < HDIM; d++) sm[tid][d] = vals[d] * inv;
    __syncthreads();
    int b = bh >> 2, h = bh & 3;
    int wid = tid >> 5, lane = tid & 31;
    for (int nl = wid; nl < 256; nl += 8) {
        float v = sm[nl][lane];
        __nv_bfloat16 hi = __float2bfloat16(v);
        __nv_bfloat16 lo = __float2bfloat16(v - __bfloat162float(hi));
        size_t o = ((size_t)b * NPIX + n0 + nl) * CDIM + h * HDIM + lane;
        g_qh[o] = hi; g_ql[o] = lo;
    }
}

// ---------------------------------------------------------------------------
// ctx[bh,d,e] += sum_n ek[d,n]*v[e,n];  z[bh,d] += sum_n ek[d,n]
// grid (64 bh, 16 chunks of 256 n).
__global__ __launch_bounds__(256) void kv_context() {
    __shared__ float ekS[HDIM][66];
    __shared__ float vT[64][36];
    int bh = blockIdx.x, nc = blockIdx.y;
    const float* kb = g_k + (size_t)bh * HDIM * NPIX + nc * 256;
    const float* vb = g_v + (size_t)bh * HDIM * NPIX + nc * 256;
    int tid = threadIdx.x;
    int d = tid >> 3, e0 = (tid & 7) << 2;
    float a0 = 0, a1 = 0, a2 = 0, a3 = 0, zacc = 0;
    float kreg[8], vreg[8];
#pragma unroll
    for (int p = 0; p < 8; p++) {
        int idx = tid + p * 256;
        int r = idx >> 6, c = idx & 63;
        kreg[p] = kb[(size_t)r * NPIX + c];
        vreg[p] = vb[(size_t)r * NPIX + c];
    }
    for (int s = 0; s < 4; s++) {
        __syncthreads();
#pragma unroll
        for (int p = 0; p < 8; p++) {
            int idx = tid + p * 256;
            int r = idx >> 6, c = idx & 63;
            ekS[r][c] = kreg[p];
            vT[c][r]  = vreg[p];
        }
        __syncthreads();
        if (s < 3) {
#pragma unroll
            for (int p = 0; p < 8; p++) {
                int idx = tid + p * 256;
                int r = idx >> 6, c = idx & 63;
                kreg[p] = kb[(size_t)r * NPIX + (s + 1) * 64 + c];
                vreg[p] = vb[(size_t)r * NPIX + (s + 1) * 64 + c];
            }
        }
#pragma unroll
        for (int n = 0; n < 64; n += 2) {
            float2 kk = *(const float2*)&ekS[d][n];
            float4 v0 = *(const float4*)&vT[n][e0];
            float4 v1 = *(const float4*)&vT[n + 1][e0];
            zacc += kk.x + kk.y;
            a0 += kk.x * v0.x; a1 += kk.x * v0.y;
            a2 += kk.x * v0.z; a3 += kk.x * v0.w;
            a0 += kk.y * v1.x; a1 += kk.y * v1.y;
            a2 += kk.y * v1.z; a3 += kk.y * v1.w;
        }
    }
    float* cp = g_ctx + (size_t)bh * 1024 + d * 32 + e0;
    atomicAdd(cp + 0, a0); atomicAdd(cp + 1, a1);
    atomicAdd(cp + 2, a2); atomicAdd(cp + 3, a3);
    if ((tid & 7) == 0) atomicAdd(&g_z[bh * HDIM + d], zacc);
}

// ---------------------------------------------------------------------------
// M[b][c, h*32+d] = sum_e w_out[c, h*32+e] * ctx[b,h,d,e] / z[b,h,d]
__global__ __launch_bounds__(128) void fold(const float* __restrict__ w_out) {
    __shared__ float ctxS[NHEADS][HDIM][HDIM];
    __shared__ float zS[CDIM];
    int b = blockIdx.x, tid = threadIdx.x;
    zS[tid] = g_z[b * CDIM + tid];
    __syncthreads();
    for (int i = tid; i < NHEADS * HDIM * HDIM; i += 128) {
        int h = i >> 10, dd = (i >> 5) & 31, e = i & 31;
        ctxS[h][dd][e] = g_ctx[(size_t)b * 4096 + i] / zS[(h << 5) + dd];
    }
    __syncthreads();
    int c = tid;
    const float* wrow = w_out + (size_t)c * CDIM;
    for (int h = 0; h < NHEADS; h++) {
        float acc[HDIM];
#pragma unroll
        for (int dd = 0; dd < HDIM; dd++) acc[dd] = 0.f;
        for (int e = 0; e < HDIM; e++) {
            float wv = wrow[(h << 5) + e];
#pragma unroll
            for (int dd = 0; dd < HDIM; dd++) acc[dd] += wv * ctxS[h][dd][e];
        }
#pragma unroll
        for (int dd = 0; dd < HDIM; dd++)
            g_M[(size_t)b * (CDIM * CDIM) + (size_t)c * CDIM + (h << 5) + dd] = acc[dd];
    }
}

// ---------------------------------------------------------------------------
// final: out[b](128x4096) = M[b] @ q_soft[b] + bias; fused GN stats. grid (32,16).
__global__ __launch_bounds__(256) void final_mma(const float* __restrict__ b_out,
                                                 float* __restrict__ out) {
    __shared__ char sA[TILE_BYTES];
    __shared__ char sB[TILE_BYTES];
    int n0 = blockIdx.x * 128, b = blockIdx.y;
    float acc[2][8][4];
#pragma unroll
    for (int mi = 0; mi < 2; mi++)
#pragma unroll
        for (int ni = 0; ni < 8; ni++)
#pragma unroll
            for (int j = 0; j < 4; j++) acc[mi][ni][j] = 0.f;

    gemm_mainloop(g_mh + (size_t)b * CDIM * CDIM, g_ml + (size_t)b * CDIM * CDIM,
                  g_qh + ((size_t)b * NPIX + n0) * CDIM,
                  g_ql + ((size_t)b * NPIX + n0) * CDIM, acc, sA, sB);

    int tid = threadIdx.x, lane = tid & 31, wid = tid >> 5;
    int warp_m = (wid & 3) * 32, warp_n = (wid >> 2) * 64;
    int grp = lane >> 2, qid = lane & 3;
    float s1 = 0.f, s2 = 0.f;
#pragma unroll
    for (int mi = 0; mi < 2; mi++) {
        int r0 = warp_m + mi * 16 + grp;
        float bias0 = b_out[r0], bias1 = b_out[r0 + 8];
#pragma unroll
        for (int ni = 0; ni < 8; ni++) {
            int col = n0 + warp_n + ni * 8 + 2 * qid;
            float2 v0 = {acc[mi][ni][0] + bias0, acc[mi][ni][1] + bias0};
            float2 v1 = {acc[mi][ni][2] + bias1, acc[mi][ni][3] + bias1};
            s1 += v0.x + v0.y + v1.x + v1.y;
            s2 += v0.x * v0.x + v0.y * v0.y + v1.x * v1.x + v1.y * v1.y;
            *(float2*)&out[((size_t)b * CDIM + r0) * NPIX + col] = v0;
            *(float2*)&out[((size_t)b * CDIM + r0 + 8) * NPIX + col] = v1;
        }
    }
#pragma unroll
    for (int off = 16; off; off >>= 1) {
        s1 += __shfl_down_sync(0xffffffffu, s1, off);
        s2 += __shfl_down_sync(0xffffffffu, s2, off);
    }
    if (lane == 0) {
        atomicAdd(&g_stats[2 * b], s1);
        atomicAdd(&g_stats[2 * b + 1], s2);
    }
}

// ---------------------------------------------------------------------------
__global__ __launch_bounds__(256) void gn_apply(const float* __restrict__ gnw,
                                                const float* __restrict__ gnb,
                                                float* __restrict__ out) {
    size_t idx = ((size_t)blockIdx.x * 256 + threadIdx.x) << 2;
    int b = (int)(idx >> 19);
    int c = (int)((idx >> 12) & 127);
    const float inv_cnt = 1.f / (float)(CDIM * NPIX);
    float mean = g_stats[2 * b] * inv_cnt;
    float var  = g_stats[2 * b + 1] * inv_cnt - mean * mean;
    float rstd = rsqrtf(var + 1e-5f);
    float scale = rstd * gnw[c];
    float shift = gnb[c] - mean * scale;
    float4 v = *(const float4*)&out[idx];
    v.x = v.x * scale + shift;
    v.y = v.y * scale + shift;
    v.z = v.z * scale + shift;
    v.w = v.w * scale + shift;
    *(float4*)&out[idx] = v;
}

// ---------------------------------------------------------------------------
extern "C" void kernel_launch(void* const* d_in, const int* in_sizes, int n_in,
                              void* d_out, int out_size) {
    (void)in_sizes; (void)n_in; (void)out_size;
    const float* x     = (const float*)d_in[0];
    const float* w_qkv = (const float*)d_in[1];
    const float* w_out = (const float*)d_in[2];
    const float* b_out = (const float*)d_in[3];
    const float* gnw   = (const float*)d_in[4];
    const float* gnb   = (const float*)d_in[5];
    float* out = (float*)d_out;

    zero_scratch<<<256, 256>>>();
    split_w<<<(OQKV * CDIM) / 256, 256>>>(w_qkv);
    split_x<<<dim3(NPIX / 32, CDIM / 32, BATCH), 256>>>(x);
    qkv_mma<<<dim3(NPIX / 128, 3, BATCH), 256>>>();
    softmax_split_q<<<BATCH * NHEADS * (NPIX / 256), 256>>>();
    kv_context<<<dim3(BATCH * NHEADS, 16), 256>>>();
    fold<<<BATCH, 128>>>(w_out);
    split_m_k<<<(BATCH * CDIM * CDIM) / 256, 256>>>();
    final_mma<<<dim3(NPIX / 128, BATCH), 256>>>(b_out, out);
    gn_apply<<<(BATCH * CDIM * NPIX) / (256 * 4), 256>>>(gnw, gnb, out);
}

// round 4
// speedup vs baseline: 1.6397x; 1.1033x over previous
#include <cuda_runtime.h>
#include <cuda_bf16.h>
#include <math.h>
#include <stdint.h>

#define BATCH 16
#define CDIM  128
#define NHEADS 4
#define HDIM  32
#define NPIX  4096
#define OQKV  384

// ---- scratch (device globals: allocation-free) ----
__device__ float g_k[BATCH * CDIM * NPIX];            // exp(k)
__device__ float g_v[BATCH * CDIM * NPIX];            // v
__device__ float g_ctx[BATCH * NHEADS * HDIM * HDIM];
__device__ float g_z[BATCH * NHEADS * HDIM];
__device__ float g_M[BATCH * CDIM * CDIM];
__device__ float g_stats[BATCH * 2];

// bf16 split operands
__device__ __nv_bfloat16 g_wh[OQKV * CDIM];
__device__ __nv_bfloat16 g_wl[OQKV * CDIM];
__device__ __nv_bfloat16 g_xh[BATCH * NPIX * CDIM];   // [b][n][c]
__device__ __nv_bfloat16 g_xl[BATCH * NPIX * CDIM];
__device__ __nv_bfloat16 g_qh[BATCH * NPIX * CDIM];   // [b][n][o] softmaxed q
__device__ __nv_bfloat16 g_ql[BATCH * NPIX * CDIM];
__device__ __nv_bfloat16 g_mh[BATCH * CDIM * CDIM];
__device__ __nv_bfloat16 g_ml[BATCH * CDIM * CDIM];

__device__ __forceinline__ uint32_t smem_u32(const void* p) {
    uint32_t a;
    asm("{ .reg .u64 t; cvta.to.shared.u64 t, %1; cvt.u32.u64 %0, t; }"
        : "=r"(a) : "l"(p));
    return a;
}
__device__ __forceinline__ void ldm_x4(uint32_t* r, uint32_t addr) {
    asm volatile("ldmatrix.sync.aligned.m8n8.x4.shared.b16 {%0,%1,%2,%3}, [%4];"
                 : "=r"(r[0]), "=r"(r[1]), "=r"(r[2]), "=r"(r[3]) : "r"(addr));
}
__device__ __forceinline__ void mma16816(float* c, const uint32_t* a,
                                         uint32_t b0, uint32_t b1) {
    asm volatile(
        "mma.sync.aligned.m16n8k16.row.col.f32.bf16.bf16.f32 "
        "{%0,%1,%2,%3}, {%4,%5,%6,%7}, {%8,%9}, {%0,%1,%2,%3};"
        : "+f"(c[0]), "+f"(c[1]), "+f"(c[2]), "+f"(c[3])
        : "r"(a[0]), "r"(a[1]), "r"(a[2]), "r"(a[3]), "r"(b0), "r"(b1));
}
__device__ __forceinline__ void cp16(uint32_t d, const void* s) {
    asm volatile("cp.async.cg.shared.global [%0], [%1], 16;" :: "r"(d), "l"(s));
}
#define CP_COMMIT() asm volatile("cp.async.commit_group;" ::: "memory")
#define CP_WAIT1()  asm volatile("cp.async.wait_group 1;" ::: "memory")
#define CP_WAIT0()  asm volatile("cp.async.wait_group 0;" ::: "memory")

// smem chunk: 128 rows x 64 bf16, row stride 9 x 16B = 144B
#define SROW 9
#define CHUNKB (128 * SROW * 16)          // 18432
#define SMEM_TOTAL (4 * CHUNKB)           // 73728: A double buf + B double buf
#define QPITCH 136                        // bf16 elements; 272B rows (16B aligned)

// ---------------------------------------------------------------------------
// cp.async double-buffered 3-term split mainloop.
// C(128x128) += [Ah,Ah,Al] @ [Bh,Bl,Bh]^T;  A [row][k], B [n][k] row-major.
__device__ __forceinline__ void gemm_pipeline(
    const __nv_bfloat16* __restrict__ Ah, const __nv_bfloat16* __restrict__ Al,
    const __nv_bfloat16* __restrict__ Bh, const __nv_bfloat16* __restrict__ Bl,
    float acc[2][8][4], uint32_t sA32, uint32_t sB32) {
    int tid = threadIdx.x;
    int lane = tid & 31, wid = tid >> 5;
    int warp_m = (wid & 3) * 32, warp_n = (wid >> 2) * 64;

    int row4[4], u4[4], soff4[4];
#pragma unroll
    for (int i = 0; i < 4; i++) {
        int lin = tid + (i << 8);
        row4[i] = lin >> 3;
        u4[i] = lin & 7;
        soff4[i] = (row4[i] * SROW + u4[i]) * 16;
    }
    int a_row = lane & 15, a_hi = lane >> 4;
    int b_n = (lane & 7) + ((lane >> 4) << 3);
    int b_ku = (lane >> 3) & 1;

    auto issue = [&](int c) {
        int term = c >> 1, half = c & 1;
        const char* As = (const char*)((term == 2 ? Al : Ah) + (half << 6));
        const char* Bs = (const char*)((term == 1 ? Bl : Bh) + (half << 6));
        uint32_t dA = sA32 + (c & 1) * CHUNKB;
        uint32_t dB = sB32 + (c & 1) * CHUNKB;
#pragma unroll
        for (int i = 0; i < 4; i++)
            cp16(dA + soff4[i], As + row4[i] * 256 + u4[i] * 16);
#pragma unroll
        for (int i = 0; i < 4; i++)
            cp16(dB + soff4[i], Bs + row4[i] * 256 + u4[i] * 16);
        CP_COMMIT();
    };

    issue(0);
    for (int c = 0; c < 6; c++) {
        __syncthreads();                  // all done computing on buf (c+1)&1
        if (c < 5) { issue(c + 1); CP_WAIT1(); }
        else       { CP_WAIT0(); }
        __syncthreads();                  // chunk c visible to all
        uint32_t aB = sA32 + (c & 1) * CHUNKB;
        uint32_t bB = sB32 + (c & 1) * CHUNKB;
#pragma unroll
        for (int kk = 0; kk < 4; kk++) {
            uint32_t af[2][4];
#pragma unroll
            for (int mi = 0; mi < 2; mi++)
                ldm_x4(af[mi], aB + ((warp_m + mi * 16 + a_row) * SROW + kk * 2 + a_hi) * 16);
            uint32_t bf[8][2];
#pragma unroll
            for (int nj = 0; nj < 4; nj++) {
                uint32_t r[4];
                ldm_x4(r, bB + ((warp_n + nj * 16 + b_n) * SROW + kk * 2 + b_ku) * 16);
                bf[nj * 2 + 0][0] = r[0]; bf[nj * 2 + 0][1] = r[1];
                bf[nj * 2 + 1][0] = r[2]; bf[nj * 2 + 1][1] = r[3];
            }
#pragma unroll
            for (int mi = 0; mi < 2; mi++)
#pragma unroll
                for (int ni = 0; ni < 8; ni++)
                    mma16816(acc[mi][ni], af[mi], bf[ni][0], bf[ni][1]);
        }
    }
}

// ===========================================================================
__global__ __launch_bounds__(256) void zero_scratch() {
    int i = blockIdx.x * 256 + threadIdx.x;
    if (i < BATCH * NHEADS * HDIM * HDIM) g_ctx[i] = 0.f;
    if (i < BATCH * NHEADS * HDIM) g_z[i] = 0.f;
    if (i < BATCH * 2) g_stats[i] = 0.f;
}

__global__ __launch_bounds__(256) void split_w(const float* __restrict__ w) {
    int i = blockIdx.x * 256 + threadIdx.x;
    float v = w[i];
    __nv_bfloat16 hi = __float2bfloat16(v);
    g_wh[i] = hi;
    g_wl[i] = __float2bfloat16(v - __bfloat162float(hi));
}

__global__ __launch_bounds__(256) void split_m_k() {
    int i = blockIdx.x * 256 + threadIdx.x;
    float v = g_M[i];
    __nv_bfloat16 hi = __float2bfloat16(v);
    g_mh[i] = hi;
    g_ml[i] = __float2bfloat16(v - __bfloat162float(hi));
}

// x [b][c][n] fp32 -> xh/xl [b][n][c] bf16 (transpose + split)
__global__ __launch_bounds__(256) void split_x(const float* __restrict__ x) {
    __shared__ float sm[32][33];
    int b = blockIdx.z, c0 = blockIdx.y * 32, n0 = blockIdx.x * 32;
    int tid = threadIdx.x;
    const float* xb = x + ((size_t)b * CDIM + c0) * NPIX + n0;
    int r = tid >> 5, col = tid & 31;
#pragma unroll
    for (int p = 0; p < 4; p++)
        sm[r + 8 * p][col] = xb[(size_t)(r + 8 * p) * NPIX + col];
    __syncthreads();
    int wid = tid >> 5, lane = tid & 31;
    for (int nl = wid; nl < 32; nl += 8) {
        float v = sm[lane][nl];
        __nv_bfloat16 hi = __float2bfloat16(v);
        __nv_bfloat16 lo = __float2bfloat16(v - __bfloat162float(hi));
        size_t o = ((size_t)b * NPIX + n0 + nl) * CDIM + c0 + lane;
        g_xh[o] = hi; g_xl[o] = lo;
    }
}

// ---------------------------------------------------------------------------
// QKV: C[b](384x4096) = W(384x128) @ X[b](128x4096). grid (32, 3, 16).
// mt=0: fused q-softmax over d + split -> qh/ql. mt=1: exp -> g_k. mt=2: g_v.
__global__ __launch_bounds__(256, 2) void qkv_mma() {
    extern __shared__ char dsm[];
    uint32_t sA32 = smem_u32(dsm), sB32 = sA32 + 2 * CHUNKB;
    int n0 = blockIdx.x * 128, mt = blockIdx.y, b = blockIdx.z;
    float acc[2][8][4];
#pragma unroll
    for (int mi = 0; mi < 2; mi++)
#pragma unroll
        for (int ni = 0; ni < 8; ni++)
#pragma unroll
            for (int j = 0; j < 4; j++) acc[mi][ni][j] = 0.f;

    gemm_pipeline(g_wh + (size_t)mt * 128 * CDIM, g_wl + (size_t)mt * 128 * CDIM,
                  g_xh + ((size_t)b * NPIX + n0) * CDIM,
                  g_xl + ((size_t)b * NPIX + n0) * CDIM, acc, sA32, sB32);

    int tid = threadIdx.x, lane = tid & 31, wid = tid >> 5;
    int warp_m = (wid & 3) * 32, warp_n = (wid >> 2) * 64;
    int grp = lane >> 2, qid = lane & 3;

    if (mt == 0) {
        // fused softmax over d (warp rows = one head) + bf16 split, staged in smem
        __syncthreads();   // mainloop smem reads done before overlaying q tiles
        __nv_bfloat16* sQh = (__nv_bfloat16*)dsm;
        __nv_bfloat16* sQl = (__nv_bfloat16*)(dsm + 128 * QPITCH * 2);
        int h = wid & 3;
        int o0 = h * 32 + grp;
#pragma unroll
        for (int ni = 0; ni < 8; ni++) {
#pragma unroll
            for (int jc = 0; jc < 2; jc++) {
                float v0 = acc[0][ni][jc],     v1 = acc[0][ni][jc + 2];
                float v2 = acc[1][ni][jc],     v3 = acc[1][ni][jc + 2];
                float m = fmaxf(fmaxf(v0, v1), fmaxf(v2, v3));
                m = fmaxf(m, __shfl_xor_sync(0xffffffffu, m, 4));
                m = fmaxf(m, __shfl_xor_sync(0xffffffffu, m, 8));
                m = fmaxf(m, __shfl_xor_sync(0xffffffffu, m, 16));
                float e0 = expf(v0 - m), e1 = expf(v1 - m);
                float e2 = expf(v2 - m), e3 = expf(v3 - m);
                float s = e0 + e1 + e2 + e3;
                s += __shfl_xor_sync(0xffffffffu, s, 4);
                s += __shfl_xor_sync(0xffffffffu, s, 8);
                s += __shfl_xor_sync(0xffffffffu, s, 16);
                float inv = 0.17677669529663687f / s;   // 32^-0.5 / sum
                e0 *= inv; e1 *= inv; e2 *= inv; e3 *= inv;
                int n = warp_n + ni * 8 + 2 * qid + jc;
                float ev[4] = {e0, e1, e2, e3};
#pragma unroll
                for (int t = 0; t < 4; t++) {
                    __nv_bfloat16 hi = __float2bfloat16(ev[t]);
                    __nv_bfloat16 lo = __float2bfloat16(ev[t] - __bfloat162float(hi));
                    sQh[n * QPITCH + o0 + t * 8] = hi;
                    sQl[n * QPITCH + o0 + t * 8] = lo;
                }
            }
        }
        __syncthreads();
        int row = tid >> 1, seg = tid & 1;
        const uint4* sH = (const uint4*)(sQh + row * QPITCH + seg * 64);
        const uint4* sL = (const uint4*)(sQl + row * QPITCH + seg * 64);
        uint4* dH = (uint4*)(g_qh + ((size_t)b * NPIX + n0 + row) * CDIM + seg * 64);
        uint4* dL = (uint4*)(g_ql + ((size_t)b * NPIX + n0 + row) * CDIM + seg * 64);
#pragma unroll
        for (int k = 0; k < 8; k++) dH[k] = sH[k];
#pragma unroll
        for (int k = 0; k < 8; k++) dL[k] = sL[k];
    } else {
        float* dst = (mt == 1) ? g_k : g_v;
        bool do_exp = (mt == 1);
#pragma unroll
        for (int mi = 0; mi < 2; mi++) {
            int r0 = warp_m + mi * 16 + grp;
#pragma unroll
            for (int ni = 0; ni < 8; ni++) {
                int col = n0 + warp_n + ni * 8 + 2 * qid;
                float2 v0 = {acc[mi][ni][0], acc[mi][ni][1]};
                float2 v1 = {acc[mi][ni][2], acc[mi][ni][3]};
                if (do_exp) {
                    v0.x = expf(v0.x); v0.y = expf(v0.y);
                    v1.x = expf(v1.x); v1.y = expf(v1.y);
                }
                *(float2*)&dst[((size_t)b * CDIM + r0) * NPIX + col] = v0;
                *(float2*)&dst[((size_t)b * CDIM + r0 + 8) * NPIX + col] = v1;
            }
        }
    }
}

// ---------------------------------------------------------------------------
// ctx[bh,d,e] += sum_n ek[d,n]*v[e,n];  z[bh,d] += sum_n ek[d,n]
// grid (64 bh, 16 chunks of 256 n).
__global__ __launch_bounds__(256) void kv_context() {
    __shared__ float ekS[HDIM][66];
    __shared__ float vT[64][36];
    int bh = blockIdx.x, nc = blockIdx.y;
    const float* kb = g_k + (size_t)bh * HDIM * NPIX + nc * 256;
    const float* vb = g_v + (size_t)bh * HDIM * NPIX + nc * 256;
    int tid = threadIdx.x;
    int d = tid >> 3, e0 = (tid & 7) << 2;
    float a0 = 0, a1 = 0, a2 = 0, a3 = 0, zacc = 0;
    float kreg[8], vreg[8];
#pragma unroll
    for (int p = 0; p < 8; p++) {
        int idx = tid + p * 256;
        int r = idx >> 6, c = idx & 63;
        kreg[p] = kb[(size_t)r * NPIX + c];
        vreg[p] = vb[(size_t)r * NPIX + c];
    }
    for (int s = 0; s < 4; s++) {
        __syncthreads();
#pragma unroll
        for (int p = 0; p < 8; p++) {
            int idx = tid + p * 256;
            int r = idx >> 6, c = idx & 63;
            ekS[r][c] = kreg[p];
            vT[c][r]  = vreg[p];
        }
        __syncthreads();
        if (s < 3) {
#pragma unroll
            for (int p = 0; p < 8; p++) {
                int idx = tid + p * 256;
                int r = idx >> 6, c = idx & 63;
                kreg[p] = kb[(size_t)r * NPIX + (s + 1) * 64 + c];
                vreg[p] = vb[(size_t)r * NPIX + (s + 1) * 64 + c];
            }
        }
#pragma unroll
        for (int n = 0; n < 64; n += 2) {
            float2 kk = *(const float2*)&ekS[d][n];
            float4 v0 = *(const float4*)&vT[n][e0];
            float4 v1 = *(const float4*)&vT[n + 1][e0];
            zacc += kk.x + kk.y;
            a0 += kk.x * v0.x; a1 += kk.x * v0.y;
            a2 += kk.x * v0.z; a3 += kk.x * v0.w;
            a0 += kk.y * v1.x; a1 += kk.y * v1.y;
            a2 += kk.y * v1.z; a3 += kk.y * v1.w;
        }
    }
    float* cp = g_ctx + (size_t)bh * 1024 + d * 32 + e0;
    atomicAdd(cp + 0, a0); atomicAdd(cp + 1, a1);
    atomicAdd(cp + 2, a2); atomicAdd(cp + 3, a3);
    if ((tid & 7) == 0) atomicAdd(&g_z[bh * HDIM + d], zacc);
}

// ---------------------------------------------------------------------------
// M[b][c, h*32+d] = sum_e w_out[c, h*32+e] * ctx[b,h,d,e] / z[b,h,d]
__global__ __launch_bounds__(128) void fold(const float* __restrict__ w_out) {
    __shared__ float ctxS[NHEADS][HDIM][HDIM];
    __shared__ float zS[CDIM];
    int b = blockIdx.x, tid = threadIdx.x;
    zS[tid] = g_z[b * CDIM + tid];
    __syncthreads();
    for (int i = tid; i < NHEADS * HDIM * HDIM; i += 128) {
        int h = i >> 10, dd = (i >> 5) & 31, e = i & 31;
        ctxS[h][dd][e] = g_ctx[(size_t)b * 4096 + i] / zS[(h << 5) + dd];
    }
    __syncthreads();
    int c = tid;
    const float* wrow = w_out + (size_t)c * CDIM;
    for (int h = 0; h < NHEADS; h++) {
        float acc[HDIM];
#pragma unroll
        for (int dd = 0; dd < HDIM; dd++) acc[dd] = 0.f;
        for (int e = 0; e < HDIM; e++) {
            float wv = wrow[(h << 5) + e];
#pragma unroll
            for (int dd = 0; dd < HDIM; dd++) acc[dd] += wv * ctxS[h][dd][e];
        }
#pragma unroll
        for (int dd = 0; dd < HDIM; dd++)
            g_M[(size_t)b * (CDIM * CDIM) + (size_t)c * CDIM + (h << 5) + dd] = acc[dd];
    }
}

// ---------------------------------------------------------------------------
// final: out[b](128x4096) = M[b] @ q_soft[b] + bias; fused GN stats. grid (32,16).
__global__ __launch_bounds__(256, 2) void final_mma(const float* __restrict__ b_out,
                                                    float* __restrict__ out) {
    extern __shared__ char dsm[];
    uint32_t sA32 = smem_u32(dsm), sB32 = sA32 + 2 * CHUNKB;
    int n0 = blockIdx.x * 128, b = blockIdx.y;
    float acc[2][8][4];
#pragma unroll
    for (int mi = 0; mi < 2; mi++)
#pragma unroll
        for (int ni = 0; ni < 8; ni++)
#pragma unroll
            for (int j = 0; j < 4; j++) acc[mi][ni][j] = 0.f;

    gemm_pipeline(g_mh + (size_t)b * CDIM * CDIM, g_ml + (size_t)b * CDIM * CDIM,
                  g_qh + ((size_t)b * NPIX + n0) * CDIM,
                  g_ql + ((size_t)b * NPIX + n0) * CDIM, acc, sA32, sB32);

    int tid = threadIdx.x, lane = tid & 31, wid = tid >> 5;
    int warp_m = (wid & 3) * 32, warp_n = (wid >> 2) * 64;
    int grp = lane >> 2, qid = lane & 3;
    float s1 = 0.f, s2 = 0.f;
#pragma unroll
    for (int mi = 0; mi < 2; mi++) {
        int r0 = warp_m + mi * 16 + grp;
        float bias0 = b_out[r0], bias1 = b_out[r0 + 8];
#pragma unroll
        for (int ni = 0; ni < 8; ni++) {
            int col = n0 + warp_n + ni * 8 + 2 * qid;
            float2 v0 = {acc[mi][ni][0] + bias0, acc[mi][ni][1] + bias0};
            float2 v1 = {acc[mi][ni][2] + bias1, acc[mi][ni][3] + bias1};
            s1 += v0.x + v0.y + v1.x + v1.y;
            s2 += v0.x * v0.x + v0.y * v0.y + v1.x * v1.x + v1.y * v1.y;
            *(float2*)&out[((size_t)b * CDIM + r0) * NPIX + col] = v0;
            *(float2*)&out[((size_t)b * CDIM + r0 + 8) * NPIX + col] = v1;
        }
    }
#pragma unroll
    for (int off = 16; off; off >>= 1) {
        s1 += __shfl_down_sync(0xffffffffu, s1, off);
        s2 += __shfl_down_sync(0xffffffffu, s2, off);
    }
    if (lane == 0) {
        atomicAdd(&g_stats[2 * b], s1);
        atomicAdd(&g_stats[2 * b + 1], s2);
    }
}

// ---------------------------------------------------------------------------
__global__ __launch_bounds__(256) void gn_apply(const float* __restrict__ gnw,
                                                const float* __restrict__ gnb,
                                                float* __restrict__ out) {
    size_t idx = ((size_t)blockIdx.x * 256 + threadIdx.x) << 2;
    int b = (int)(idx >> 19);
    int c = (int)((idx >> 12) & 127);
    const float inv_cnt = 1.f / (float)(CDIM * NPIX);
    float mean = g_stats[2 * b] * inv_cnt;
    float var  = g_stats[2 * b + 1] * inv_cnt - mean * mean;
    float rstd = rsqrtf(var + 1e-5f);
    float scale = rstd * gnw[c];
    float shift = gnb[c] - mean * scale;
    float4 v = *(const float4*)&out[idx];
    v.x = v.x * scale + shift;
    v.y = v.y * scale + shift;
    v.z = v.z * scale + shift;
    v.w = v.w * scale + shift;
    *(float4*)&out[idx] = v;
}

// ---------------------------------------------------------------------------
extern "C" void kernel_launch(void* const* d_in, const int* in_sizes, int n_in,
                              void* d_out, int out_size) {
    (void)in_sizes; (void)n_in; (void)out_size;
    const float* x     = (const float*)d_in[0];
    const float* w_qkv = (const float*)d_in[1];
    const float* w_out = (const float*)d_in[2];
    const float* b_out = (const float*)d_in[3];
    const float* gnw   = (const float*)d_in[4];
    const float* gnb   = (const float*)d_in[5];
    float* out = (float*)d_out;

    cudaFuncSetAttribute(qkv_mma, cudaFuncAttributeMaxDynamicSharedMemorySize, SMEM_TOTAL);
    cudaFuncSetAttribute(final_mma, cudaFuncAttributeMaxDynamicSharedMemorySize, SMEM_TOTAL);

    zero_scratch<<<256, 256>>>();
    split_w<<<(OQKV * CDIM) / 256, 256>>>(w_qkv);
    split_x<<<dim3(NPIX / 32, CDIM / 32, BATCH), 256>>>(x);
    qkv_mma<<<dim3(NPIX / 128, 3, BATCH), 256, SMEM_TOTAL>>>();
    kv_context<<<dim3(BATCH * NHEADS, 16), 256>>>();
    fold<<<BATCH, 128>>>(w_out);
    split_m_k<<<(BATCH * CDIM * CDIM) / 256, 256>>>();
    final_mma<<<dim3(NPIX / 128, BATCH), 256, SMEM_TOTAL>>>(b_out, out);
    gn_apply<<<(BATCH * CDIM * NPIX) / (256 * 4), 256>>>(gnw, gnb, out);
}